// round 2
// baseline (speedup 1.0000x reference)
#include <cuda_runtime.h>
#include <cuda_bf16.h>

// TokenCombiner: out[r] = inp[in_off[j] + (r - out_off[j])] for the chunk j
// owning output row r (out_off sorted ascending); rows past a chunk's split
// keep the original `out` buffer value.
//
// Inputs (metadata order):
//   d_in[0] : float32 inp  [IN_LEN * HIDDEN]
//   d_in[1] : float32 out  [OUT_LEN * HIDDEN]  (fallback values for padding rows)
//   d_in[2] : int32 in_splits_offsets  [2, NSPLITS] (row0 = splits, row1 = offsets)
//            (reference creates int64 numpy but jnp.asarray canonicalizes to int32)
//   d_in[3] : int32 out_splits_offsets [2, NSPLITS]
// Output: float32 [OUT_LEN * HIDDEN]

#ifndef HIDDEN_F32
#define HIDDEN_F32 4096
#endif
#define VEC_PER_ROW (HIDDEN_F32 / 4)   // 1024 float4 per row
#define MAX_SPLITS 64

__global__ void token_combine_kernel(
    const float4* __restrict__ inp,
    const float4* __restrict__ outbuf,
    const int* __restrict__ in_so,    // [2, nsplits] int32
    const int* __restrict__ out_so,   // [2, nsplits] int32
    float4* __restrict__ out,
    int nsplits,
    int total_vec)
{
    __shared__ int s_in_off[MAX_SPLITS];
    __shared__ int s_out_split[MAX_SPLITS];
    __shared__ int s_out_off[MAX_SPLITS];

    if (threadIdx.x < nsplits) {
        s_in_off[threadIdx.x]    = in_so[nsplits + threadIdx.x];
        s_out_split[threadIdx.x] = out_so[threadIdx.x];
        s_out_off[threadIdx.x]   = out_so[nsplits + threadIdx.x];
    }
    __syncthreads();

    int idx = blockIdx.x * blockDim.x + threadIdx.x;
    if (idx >= total_vec) return;

    int row = idx >> 10;               // idx / VEC_PER_ROW (1024)
    int col = idx & (VEC_PER_ROW - 1);

    // Find chunk j = last k with out_off[k] <= row (out_off sorted ascending).
    // nsplits is tiny (8); warp-uniform since a block spans one row's columns.
    int j = 0;
    #pragma unroll 8
    for (int k = 1; k < nsplits; k++) {
        if (s_out_off[k] <= row) j = k;
    }

    int pos = row - s_out_off[j];
    float4 v;
    if (pos < s_out_split[j]) {
        long long src_row = (long long)(s_in_off[j] + pos);
        v = inp[src_row * (long long)VEC_PER_ROW + col];
    } else {
        v = outbuf[idx];
    }
    out[idx] = v;
}

extern "C" void kernel_launch(void* const* d_in, const int* in_sizes, int n_in,
                              void* d_out, int out_size)
{
    const float4* inp    = (const float4*)d_in[0];
    const float4* outbuf = (const float4*)d_in[1];
    const int* in_so  = (const int*)d_in[2];
    const int* out_so = (const int*)d_in[3];
    float4* out = (float4*)d_out;

    int nsplits = in_sizes[2] / 2;
    int total_vec = out_size / 4;          // float4 count

    const int threads = 256;
    int blocks = (total_vec + threads - 1) / threads;

    token_combine_kernel<<<blocks, threads>>>(
        inp, outbuf, in_so, out_so, out, nsplits, total_vec);
}

// round 3
// speedup vs baseline: 1.1030x; 1.1030x over previous
#include <cuda_runtime.h>
#include <cuda_bf16.h>

// TokenCombiner: out[r] = inp[in_off[j] + (r - out_off[j])] for the chunk j
// owning output row r (out_off sorted ascending); rows past a chunk's split
// keep the original `out` buffer value.
//
// Inputs (metadata order):
//   d_in[0] : float32 inp  [IN_LEN * HIDDEN]
//   d_in[1] : float32 out  [OUT_LEN * HIDDEN]  (fallback values for padding rows)
//   d_in[2] : int32 in_splits_offsets  [2, NSPLITS]
//   d_in[3] : int32 out_splits_offsets [2, NSPLITS]
// Output: float32 [OUT_LEN * HIDDEN]

#ifndef HIDDEN_F32
#define HIDDEN_F32 4096
#endif
#define VEC_PER_ROW (HIDDEN_F32 / 4)   // 1024 float4 per row
#define LOG2_VPR 10
#define MAX_SPLITS 64
#define UNROLL 8
#define THREADS 256

__global__ __launch_bounds__(THREADS)
void token_combine_kernel(
    const float4* __restrict__ inp,
    const float4* __restrict__ outbuf,
    const int* __restrict__ in_so,    // [2, nsplits] int32
    const int* __restrict__ out_so,   // [2, nsplits] int32
    float4* __restrict__ out,
    int nsplits,
    int total_vec)
{
    __shared__ int s_in_off[MAX_SPLITS];
    __shared__ int s_out_split[MAX_SPLITS];
    __shared__ int s_out_off[MAX_SPLITS];

    if (threadIdx.x < nsplits) {
        s_in_off[threadIdx.x]    = in_so[nsplits + threadIdx.x];
        s_out_split[threadIdx.x] = out_so[threadIdx.x];
        s_out_off[threadIdx.x]   = out_so[nsplits + threadIdx.x];
    }
    __syncthreads();

    // Each block owns a contiguous tile of THREADS*UNROLL float4.
    // Thread t handles idx = tile_base + k*THREADS + t (k = 0..UNROLL-1):
    // consecutive threads stay coalesced, and the UNROLL loads per thread are
    // independent (front-batched -> high MLP).
    int tile_base = blockIdx.x * (THREADS * UNROLL) + threadIdx.x;

    float4 v[UNROLL];

    #pragma unroll
    for (int k = 0; k < UNROLL; k++) {
        int idx = tile_base + k * THREADS;
        if (idx < total_vec) {
            int row = idx >> LOG2_VPR;
            int col = idx & (VEC_PER_ROW - 1);

            int j = 0;
            #pragma unroll 8
            for (int q = 1; q < nsplits; q++) {
                if (s_out_off[q] <= row) j = q;
            }
            int pos = row - s_out_off[j];
            if (pos < s_out_split[j]) {
                long long src = ((long long)(s_in_off[j] + pos) << LOG2_VPR) + col;
                v[k] = inp[src];
            } else {
                v[k] = outbuf[idx];
            }
        }
    }

    #pragma unroll
    for (int k = 0; k < UNROLL; k++) {
        int idx = tile_base + k * THREADS;
        if (idx < total_vec) {
            out[idx] = v[k];
        }
    }
}

extern "C" void kernel_launch(void* const* d_in, const int* in_sizes, int n_in,
                              void* d_out, int out_size)
{
    const float4* inp    = (const float4*)d_in[0];
    const float4* outbuf = (const float4*)d_in[1];
    const int* in_so  = (const int*)d_in[2];
    const int* out_so = (const int*)d_in[3];
    float4* out = (float4*)d_out;

    int nsplits = in_sizes[2] / 2;
    int total_vec = out_size / 4;          // float4 count

    int per_block = THREADS * UNROLL;
    int blocks = (total_vec + per_block - 1) / per_block;

    token_combine_kernel<<<blocks, THREADS>>>(
        inp, outbuf, in_so, out_so, out, nsplits, total_vec);
}